// round 10
// baseline (speedup 1.0000x reference)
#include <cuda_runtime.h>
#include <cuda_bf16.h>
#include <mma.h>
#include <math.h>
#include <stdint.h>

using namespace nvcuda;

// Problem constants
#define B_  2
#define L_  2048
#define D_  256
#define H_  8
#define h_  32
#define C_  64            // chunk size
#define NC_ (L_ / C_)     // 32 chunks per (b,h)
#define BH_ (B_ * H_)     // 16
#define NPOS_ (BH_ * L_)  // 32768
#define EPS_ 1e-5f
#define P36 36            // float4-friendly smem pitch

// -------- scratch (device globals, no allocation) --------
__device__ float g_Q[NPOS_ * h_];      // [B,H,L,h]
__device__ float g_K[NPOS_ * h_];
__device__ float g_V[NPOS_ * h_];
__device__ float g_Sincl[BH_ * NC_ * h_ * h_];   // inclusive chain
__device__ float g_minc[BH_ * NC_];
__device__ float g_sinc[BH_ * NC_];
__device__ float g_ginc[BH_ * NC_];
__device__ int   g_flag[BH_ * NC_];

// bf16 split buffers (hi + lo ~ fp32 via 3x bf16 MMA)
__device__ __align__(16) __nv_bfloat16 g_xhi[B_ * L_ * D_];
__device__ __align__(16) __nv_bfloat16 g_xlo[B_ * L_ * D_];
__device__ __align__(16) __nv_bfloat16 g_whi[4 * D_ * D_];   // q,k,v,o
__device__ __align__(16) __nv_bfloat16 g_wlo[4 * D_ * D_];
__device__ __align__(16) __nv_bfloat16 g_chi[B_ * L_ * D_];
__device__ __align__(16) __nv_bfloat16 g_clo[B_ * L_ * D_];

// -------- helpers --------
__device__ __forceinline__ float warpSum(float v) {
#pragma unroll
    for (int o = 16; o > 0; o >>= 1) v += __shfl_xor_sync(0xffffffffu, v, o);
    return v;
}
__device__ __forceinline__ float warpMax(float v) {
#pragma unroll
    for (int o = 16; o > 0; o >>= 1) v = fmaxf(v, __shfl_xor_sync(0xffffffffu, v, o));
    return v;
}

// =====================================================================
// convert: fp32 -> (bf16 hi, bf16 lo)
// =====================================================================
__global__ void convert_split_kernel(const float* __restrict__ src,
                                     __nv_bfloat16* __restrict__ hi,
                                     __nv_bfloat16* __restrict__ lo) {
    int i = blockIdx.x * 256 + threadIdx.x;
    float4 v = ((const float4*)src)[i];
    __nv_bfloat16 h0 = __float2bfloat16(v.x);
    __nv_bfloat16 h1 = __float2bfloat16(v.y);
    __nv_bfloat16 h2 = __float2bfloat16(v.z);
    __nv_bfloat16 h3 = __float2bfloat16(v.w);
    __nv_bfloat16 l0 = __float2bfloat16(v.x - __bfloat162float(h0));
    __nv_bfloat16 l1 = __float2bfloat16(v.y - __bfloat162float(h1));
    __nv_bfloat16 l2 = __float2bfloat16(v.z - __bfloat162float(h2));
    __nv_bfloat16 l3 = __float2bfloat16(v.w - __bfloat162float(h3));
    __nv_bfloat162* H = (__nv_bfloat162*)hi;
    __nv_bfloat162* Lo = (__nv_bfloat162*)lo;
    H[2 * i] = __nv_bfloat162(h0, h1);
    H[2 * i + 1] = __nv_bfloat162(h2, h3);
    Lo[2 * i] = __nv_bfloat162(l0, l1);
    Lo[2 * i + 1] = __nv_bfloat162(l2, l3);
}

// all 4 weight matrices in one launch: grid = 4*64 blocks
__global__ void convert_w_kernel(const float* __restrict__ w0,
                                 const float* __restrict__ w1,
                                 const float* __restrict__ w2,
                                 const float* __restrict__ w3) {
    int mat = blockIdx.x >> 6;
    int i = (blockIdx.x & 63) * 256 + threadIdx.x;  // float4 index
    const float* src = (mat == 0) ? w0 : (mat == 1) ? w1 : (mat == 2) ? w2 : w3;
    float4 v = ((const float4*)src)[i];
    __nv_bfloat16 h0 = __float2bfloat16(v.x);
    __nv_bfloat16 h1 = __float2bfloat16(v.y);
    __nv_bfloat16 h2 = __float2bfloat16(v.z);
    __nv_bfloat16 h3 = __float2bfloat16(v.w);
    __nv_bfloat16 l0 = __float2bfloat16(v.x - __bfloat162float(h0));
    __nv_bfloat16 l1 = __float2bfloat16(v.y - __bfloat162float(h1));
    __nv_bfloat16 l2 = __float2bfloat16(v.z - __bfloat162float(h2));
    __nv_bfloat16 l3 = __float2bfloat16(v.w - __bfloat162float(h3));
    size_t o2 = (size_t)mat * (D_ * D_ / 2) + 2 * (size_t)i;
    __nv_bfloat162* H = (__nv_bfloat162*)g_whi;
    __nv_bfloat162* Lo = (__nv_bfloat162*)g_wlo;
    H[o2] = __nv_bfloat162(h0, h1);
    H[o2 + 1] = __nv_bfloat162(h2, h3);
    Lo[o2] = __nv_bfloat162(l0, l1);
    Lo[o2 + 1] = __nv_bfloat162(l2, l3);
}

// =====================================================================
// WMMA split-bf16 GEMM (unchanged from R9 winner).
// =====================================================================
#define TM_ 128
#define TN_ 64
#define KSL 32
#define XP 40   // bf16 smem pitch
#define CP 72   // float epilogue pitch

__global__ __launch_bounds__(256)
void mma_gemm_kernel(const __nv_bfloat16* __restrict__ Ahi,
                     const __nv_bfloat16* __restrict__ Alo,
                     const float* __restrict__ bias0,
                     const float* __restrict__ bias1,
                     const float* __restrict__ bias2,
                     float* __restrict__ Out0,
                     float* __restrict__ Out1,
                     float* __restrict__ Out2,
                     int wbase, int mode) {
    __shared__ __align__(16) union {
        struct {
            __nv_bfloat16 xh[TM_ * XP];
            __nv_bfloat16 xl[TM_ * XP];
            __nv_bfloat16 wh[TN_ * XP];
            __nv_bfloat16 wl[TN_ * XP];
        } s;
        float cbuf[TM_ * CP];
    } u;

    const int tid = threadIdx.x;
    const int wid = tid >> 5;
    const int wm = wid & 3;
    const int wn = wid >> 2;
    const int rowBase = blockIdx.x * TM_;
    const int gc0 = blockIdx.y * TN_;
    const int mat = gc0 >> 8;
    const int colLoc = gc0 & 255;

    const __nv_bfloat16* Whi =
        g_whi + (size_t)(wbase + mat) * (D_ * D_) + (size_t)colLoc * D_;
    const __nv_bfloat16* Wlo =
        g_wlo + (size_t)(wbase + mat) * (D_ * D_) + (size_t)colLoc * D_;

    wmma::fragment<wmma::accumulator, 16, 16, 16, float> c[2][2];
#pragma unroll
    for (int i = 0; i < 2; i++)
#pragma unroll
        for (int j = 0; j < 2; j++) wmma::fill_fragment(c[i][j], 0.f);

    for (int s = 0; s < D_ / KSL; s++) {
        {
            const __nv_bfloat16* Ah = Ahi + (size_t)rowBase * D_ + s * KSL;
            const __nv_bfloat16* Al = Alo + (size_t)rowBase * D_ + s * KSL;
#pragma unroll
            for (int t = 0; t < 2; t++) {
                int i = tid + t * 256;
                int r = i >> 2, cg = (i & 3) * 8;
                *(uint4*)&u.s.xh[r * XP + cg] = *(const uint4*)(Ah + (size_t)r * D_ + cg);
                *(uint4*)&u.s.xl[r * XP + cg] = *(const uint4*)(Al + (size_t)r * D_ + cg);
            }
            const __nv_bfloat16* Bh = Whi + s * KSL;
            const __nv_bfloat16* Bl = Wlo + s * KSL;
            int r = tid >> 2, cg = (tid & 3) * 8;
            *(uint4*)&u.s.wh[r * XP + cg] = *(const uint4*)(Bh + (size_t)r * D_ + cg);
            *(uint4*)&u.s.wl[r * XP + cg] = *(const uint4*)(Bl + (size_t)r * D_ + cg);
        }
        __syncthreads();

#pragma unroll
        for (int kk = 0; kk < KSL; kk += 16) {
            wmma::fragment<wmma::matrix_a, 16, 16, 16, __nv_bfloat16, wmma::row_major> ah[2], al[2];
            wmma::fragment<wmma::matrix_b, 16, 16, 16, __nv_bfloat16, wmma::col_major> bh[2], bl[2];
#pragma unroll
            for (int i = 0; i < 2; i++) {
                wmma::load_matrix_sync(ah[i], &u.s.xh[(wm * 32 + i * 16) * XP + kk], XP);
                wmma::load_matrix_sync(al[i], &u.s.xl[(wm * 32 + i * 16) * XP + kk], XP);
            }
#pragma unroll
            for (int j = 0; j < 2; j++) {
                wmma::load_matrix_sync(bh[j], &u.s.wh[(wn * 32 + j * 16) * XP + kk], XP);
                wmma::load_matrix_sync(bl[j], &u.s.wl[(wn * 32 + j * 16) * XP + kk], XP);
            }
#pragma unroll
            for (int i = 0; i < 2; i++)
#pragma unroll
                for (int j = 0; j < 2; j++) {
                    wmma::mma_sync(c[i][j], ah[i], bh[j], c[i][j]);
                    wmma::mma_sync(c[i][j], ah[i], bl[j], c[i][j]);
                    wmma::mma_sync(c[i][j], al[i], bh[j], c[i][j]);
                }
        }
        __syncthreads();
    }

#pragma unroll
    for (int i = 0; i < 2; i++)
#pragma unroll
        for (int j = 0; j < 2; j++)
            wmma::store_matrix_sync(&u.cbuf[(wm * 32 + i * 16) * CP + wn * 32 + j * 16],
                                    c[i][j], CP, wmma::mem_row_major);
    __syncthreads();

    const float* Bv = (mat == 0) ? bias0 : (mat == 1) ? bias1 : bias2;
    float* Out = (mat == 0) ? Out0 : (mat == 1) ? Out1 : Out2;

#pragma unroll
    for (int t = 0; t < 8; t++) {
        int f = tid + t * 256;
        int r = f >> 4;
        int col = (f & 15) * 4;
        float4 o;
        o.x = u.cbuf[r * CP + col + 0] + Bv[colLoc + col + 0];
        o.y = u.cbuf[r * CP + col + 1] + Bv[colLoc + col + 1];
        o.z = u.cbuf[r * CP + col + 2] + Bv[colLoc + col + 2];
        o.w = u.cbuf[r * CP + col + 3] + Bv[colLoc + col + 3];
        int row = rowBase + r;
        if (mode == 0) {
            int b = row >> 11;
            int l = row & (L_ - 1);
            int gcol = gc0 + col;
            int head = (gcol >> 5) & 7;
            int e = gcol & 31;
            size_t ob = ((size_t)((b * H_ + head) * L_ + l)) * h_ + e;
            *(float4*)(Out + ob) = o;
        } else {
            *(float4*)(Out0 + (size_t)row * D_ + gc0 + col) = o;
        }
    }
}

// =====================================================================
// Fused attention: pointwise + Sdelta + decoupled-lookback chunk scan +
// intra-chunk scans + output (written as bf16 hi/lo split).
// grid = BH*NC = 512 blocks (id = bh*32 + c), 256 threads.
// =====================================================================
__global__ __launch_bounds__(256)
void attn_fused_kernel(const float* __restrict__ kv_scale,
                       const float* __restrict__ qk_scale,
                       const float* __restrict__ wg_w,
                       const float* __restrict__ wg_b) {
    __shared__ __align__(16) float qsm[C_ * P36];
    __shared__ __align__(16) float ksm[C_ * P36];
    __shared__ __align__(16) float vsm[C_ * P36];
    __shared__ __align__(16) float S0[h_ * P36];  // first msh (pitch 33), then S0 (pitch 36)
    __shared__ float gsh[C_];
    __shared__ float simsh[C_];
    __shared__ float gcum[C_];
    __shared__ float msm[C_];
    __shared__ float ssm[C_];
    __shared__ float sc3[3];  // exclusive m0, s0, g0

    const int id = blockIdx.x;
    const int c = id & (NC_ - 1);
    const int bh = id >> 5;
    const int head = bh & (H_ - 1);
    const int b = bh >> 3;
    const int base = bh * L_ + c * C_;
    const int tid = threadIdx.x;
    const int lane = tid & 31;
    const int w = tid >> 5;

    // ---- stage gate matrix M = wg_w ∘ kv_scale[head] into S0 (pitch 33) ----
    for (int i = tid; i < h_ * h_; i += 256)
        S0[(i >> 5) * 33 + (i & 31)] =
            wg_w[i] * kv_scale[(size_t)head * (h_ * h_) + i];
    __syncthreads();

    float qksc = qk_scale[head];
    float gb = wg_b[0];

    // ---- pointwise: 8 positions per warp, lane = dim ----
#pragma unroll
    for (int j = 0; j < C_ / 8; j++) {
        int l = w * (C_ / 8) + j;
        size_t gidx = (size_t)(base + l) * h_ + lane;
        float q = g_Q[gidx];
        float k = g_K[gidx];
        float v = g_V[gidx];

        float sim = warpSum(q * k) * qksc;
        float kn = sqrtf(warpSum(k * k));
        k = k / fmaxf(kn, 1e-12f);
        float vn = sqrtf(warpSum(v * v));
        v = v / fmaxf(vn, 1e-12f);

        // gate logit: read M rows from smem (broadcast-free pattern)
        float inner = 0.f;
#pragma unroll
        for (int e = 0; e < 32; e++)
            inner = fmaf(S0[lane * 33 + e], __shfl_sync(0xffffffffu, k, e), inner);
        float logit = warpSum(v * inner) + gb;
        float r = fmaxf(logit, 0.f);
        float g = r * r + EPS_;

        qsm[l * P36 + lane] = q;
        ksm[l * P36 + lane] = k;
        vsm[l * P36 + lane] = v;
        if (lane == 0) {
            gsh[l] = g;
            simsh[l] = sim;
            gcum[l] = g;
            msm[l] = sim;
            ssm[l] = 1.f;
        }
    }
    __syncthreads();

    // ---- Sdelta[d][e] = sum_i g_i v[i][d] k[i][e]; warp w: e=lane, d=w+8j
    float acc4[4] = {0.f, 0.f, 0.f, 0.f};
    for (int i = 0; i < C_; i++) {
        float gk = gsh[i] * ksm[i * P36 + lane];
#pragma unroll
        for (int j = 0; j < 4; j++) acc4[j] += vsm[i * P36 + w + 8 * j] * gk;
    }

    // ---- local scalar reductions (warp 0; thread 0 keeps results) ----
    float mloc = 0.f, sloc = 0.f, gsum = 0.f;
    if (tid < 32) {
        float lm = -INFINITY, lg = 0.f;
#pragma unroll
        for (int j = 0; j < C_ / 32; j++) {
            lm = fmaxf(lm, simsh[lane + 32 * j]);
            lg += gsh[lane + 32 * j];
        }
        mloc = warpMax(lm);
        float ls = 0.f;
#pragma unroll
        for (int j = 0; j < C_ / 32; j++) ls += expf(simsh[lane + 32 * j] - mloc);
        sloc = warpSum(ls);
        gsum = warpSum(lg);
    }

    // ---- decoupled lookback: wait for predecessor, publish inclusive ----
    if (tid == 0 && c > 0) {
        while (atomicAdd(&g_flag[id - 1], 0) == 0) __nanosleep(64);
    }
    __syncthreads();

    {
        size_t sb = (size_t)id * (h_ * h_);
        size_t pb = (size_t)(id - 1) * (h_ * h_);
#pragma unroll
        for (int j = 0; j < 4; j++) {
            int idx = tid + 256 * j;            // = (w+8j)*32 + lane
            float excl = (c > 0) ? __ldcg(&g_Sincl[pb + idx]) : 0.f;
            float sc = kv_scale[(size_t)head * (h_ * h_) + idx];
            g_Sincl[sb + idx] = excl + acc4[j] * sc;
            S0[(w + 8 * j) * P36 + lane] = excl;
        }
        if (tid == 0) {
            float mp = -INFINITY, sp = 0.f, gp = 0.f;
            if (c > 0) {
                mp = __ldcg(&g_minc[id - 1]);
                sp = __ldcg(&g_sinc[id - 1]);
                gp = __ldcg(&g_ginc[id - 1]);
            }
            sc3[0] = mp; sc3[1] = sp; sc3[2] = gp;
            float mn = fmaxf(mp, mloc);
            g_minc[id] = mn;
            g_sinc[id] = sp * expf(mp - mn) + sloc * expf(mloc - mn);
            g_ginc[id] = gp + gsum;
        }
    }
    __threadfence();
    __syncthreads();
    if (tid == 0) atomicExch(&g_flag[id], 1);

    // ---- intra-chunk Hillis-Steele scans over C_=64 elements ----
    for (int off = 1; off < C_; off <<= 1) {
        float ga = 0.f, m2 = 0.f, s2 = 0.f;
        bool rd = (tid < C_) && (tid >= off);
        if (rd) {
            ga = gcum[tid - off];
            m2 = msm[tid - off];
            s2 = ssm[tid - off];
        }
        __syncthreads();
        if (rd) {
            gcum[tid] += ga;
            float m1 = msm[tid], s1 = ssm[tid];
            float mn = fmaxf(m1, m2);
            ssm[tid] = s1 * expf(m1 - mn) + s2 * expf(m2 - mn);
            msm[tid] = mn;
        }
        __syncthreads();
    }

    float m0 = sc3[0], s0 = sc3[1], g0 = sc3[2];

    // ---- output: 4 threads per row l, 8 cols each ----
    int l = tid >> 2;
    int quad = tid & 3;
    int eb = quad * 8;
    unsigned gmask = 0xFu << (lane & ~3);

    float qf[32];
#pragma unroll
    for (int m = 0; m < 8; m++) {
        float4 qv = *(const float4*)&qsm[l * P36 + m * 4];
        qf[m * 4 + 0] = qv.x;
        qf[m * 4 + 1] = qv.y;
        qf[m * 4 + 2] = qv.z;
        qf[m * 4 + 3] = qv.w;
    }

    float acc[8];
#pragma unroll
    for (int j = 0; j < 8; j++) acc[j] = 0.f;

    // Part A: q_l @ S0 (exclusive chunk prefix)
#pragma unroll 8
    for (int d = 0; d < 32; d++) {
        float4 sa = *(const float4*)&S0[d * P36 + eb];
        float4 sb = *(const float4*)&S0[d * P36 + eb + 4];
        float qv = qf[d];
        acc[0] = fmaf(qv, sa.x, acc[0]);
        acc[1] = fmaf(qv, sa.y, acc[1]);
        acc[2] = fmaf(qv, sa.z, acc[2]);
        acc[3] = fmaf(qv, sa.w, acc[3]);
        acc[4] = fmaf(qv, sb.x, acc[4]);
        acc[5] = fmaf(qv, sb.y, acc[5]);
        acc[6] = fmaf(qv, sb.z, acc[6]);
        acc[7] = fmaf(qv, sb.w, acc[7]);
    }

    // Part B: causal intra-chunk
    float qe0 = qf[eb + 0], qe1 = qf[eb + 1], qe2 = qf[eb + 2], qe3 = qf[eb + 3];
    float qe4 = qf[eb + 4], qe5 = qf[eb + 5], qe6 = qf[eb + 6], qe7 = qf[eb + 7];
    for (int i = 0; i <= l; i++) {
        float4 va = *(const float4*)&vsm[i * P36 + eb];
        float4 vb = *(const float4*)&vsm[i * P36 + eb + 4];
        float p = qe0 * va.x + qe1 * va.y + qe2 * va.z + qe3 * va.w +
                  qe4 * vb.x + qe5 * vb.y + qe6 * vb.z + qe7 * vb.w;
        p += __shfl_xor_sync(gmask, p, 1);
        p += __shfl_xor_sync(gmask, p, 2);
        p *= gsh[i];
        float4 ka = *(const float4*)&ksm[i * P36 + eb];
        float4 kb = *(const float4*)&ksm[i * P36 + eb + 4];
        acc[0] = fmaf(p, ka.x, acc[0]);
        acc[1] = fmaf(p, ka.y, acc[1]);
        acc[2] = fmaf(p, ka.z, acc[2]);
        acc[3] = fmaf(p, ka.w, acc[3]);
        acc[4] = fmaf(p, kb.x, acc[4]);
        acc[5] = fmaf(p, kb.y, acc[5]);
        acc[6] = fmaf(p, kb.z, acc[6]);
        acc[7] = fmaf(p, kb.w, acc[7]);
    }

    // final scaling
    float ml = msm[l], sl = ssm[l];
    float mn = fmaxf(m0, ml);
    float sfull = s0 * expf(m0 - mn) + sl * expf(ml - mn);
    float ww = expf(simsh[l] - mn) / (sfull + EPS_);
    float silu = ww / (1.f + expf(-ww));
    float gc = gcum[l] + g0;
    float factor = (1.f + silu) / (gc + EPS_);

    // write ctxt directly as bf16 hi/lo split
    int lg = c * C_ + l;
    size_t obase = ((size_t)b * L_ + lg) * D_ + head * h_ + eb;
    __nv_bfloat16 hi8[8], lo8[8];
#pragma unroll
    for (int j = 0; j < 8; j++) {
        float o = acc[j] * factor;
        hi8[j] = __float2bfloat16(o);
        lo8[j] = __float2bfloat16(o - __bfloat162float(hi8[j]));
    }
    *(uint4*)(g_chi + obase) = *(uint4*)hi8;
    *(uint4*)(g_clo + obase) = *(uint4*)lo8;
}

// =====================================================================
// launch
// =====================================================================
extern "C" void kernel_launch(void* const* d_in, const int* in_sizes, int n_in,
                              void* d_out, int out_size) {
    const float* x = (const float*)d_in[0];
    const float* wq_w = (const float*)d_in[1];
    const float* wq_b = (const float*)d_in[2];
    const float* wk_w = (const float*)d_in[3];
    const float* wk_b = (const float*)d_in[4];
    const float* wv_w = (const float*)d_in[5];
    const float* wv_b = (const float*)d_in[6];
    const float* wo_w = (const float*)d_in[7];
    const float* wo_b = (const float*)d_in[8];
    const float* wg_w = (const float*)d_in[9];
    const float* wg_b = (const float*)d_in[10];
    const float* kv_scale = (const float*)d_in[11];
    const float* qk_scale = (const float*)d_in[12];
    float* out = (float*)d_out;

    float* Qp; cudaGetSymbolAddress((void**)&Qp, g_Q);
    float* Kp; cudaGetSymbolAddress((void**)&Kp, g_K);
    float* Vp; cudaGetSymbolAddress((void**)&Vp, g_V);
    __nv_bfloat16* xhi; cudaGetSymbolAddress((void**)&xhi, g_xhi);
    __nv_bfloat16* xlo; cudaGetSymbolAddress((void**)&xlo, g_xlo);
    __nv_bfloat16* chi; cudaGetSymbolAddress((void**)&chi, g_chi);
    __nv_bfloat16* clo; cudaGetSymbolAddress((void**)&clo, g_clo);
    int* flags; cudaGetSymbolAddress((void**)&flags, g_flag);

    // reset lookback flags (graph-capturable memset node)
    cudaMemsetAsync(flags, 0, BH_ * NC_ * sizeof(int));

    // converts
    convert_split_kernel<<<(B_ * L_ * D_) / 4 / 256, 256>>>(x, xhi, xlo);
    convert_w_kernel<<<4 * 64, 256>>>(wq_w, wk_w, wv_w, wo_w);

    // fused QKV projection (WMMA bf16 split)
    dim3 gqkv(B_ * L_ / TM_, 3 * D_ / TN_);
    mma_gemm_kernel<<<gqkv, 256>>>(xhi, xlo, wq_b, wk_b, wv_b,
                                   Qp, Kp, Vp, 0, 0);

    // fused attention with decoupled lookback
    attn_fused_kernel<<<BH_ * NC_, 256>>>(kv_scale, qk_scale, wg_w, wg_b);

    // output projection (reads chi/clo written by attn_fused)
    dim3 gout(B_ * L_ / TM_, D_ / TN_);
    mma_gemm_kernel<<<gout, 256>>>(chi, clo, wo_b, wo_b, wo_b,
                                   out, out, out, 3, 1);
}

// round 11
// speedup vs baseline: 1.5004x; 1.5004x over previous
#include <cuda_runtime.h>
#include <cuda_bf16.h>
#include <mma.h>
#include <math.h>
#include <stdint.h>

using namespace nvcuda;

// Problem constants
#define B_  2
#define L_  2048
#define D_  256
#define H_  8
#define h_  32
#define C_  64            // chunk size
#define NC_ (L_ / C_)     // 32 chunks per (b,h)
#define BH_ (B_ * H_)     // 16
#define NPOS_ (BH_ * L_)  // 32768
#define EPS_ 1e-5f
#define P36 36            // float4-friendly smem pitch

// -------- scratch (device globals, no allocation) --------
__device__ float g_Q[NPOS_ * h_];      // [B,H,L,h]
__device__ float g_K[NPOS_ * h_];
__device__ float g_V[NPOS_ * h_];
__device__ float g_sim[NPOS_];
__device__ float g_gate[NPOS_];
__device__ float g_Sdelta[BH_ * NC_ * h_ * h_];
__device__ float g_Sprefix[BH_ * NC_ * h_ * h_];
__device__ float g_gsum[BH_ * NC_];
__device__ float g_mloc[BH_ * NC_];
__device__ float g_sloc[BH_ * NC_];
__device__ float g_gpre[BH_ * NC_];
__device__ float g_mpre[BH_ * NC_];
__device__ float g_spre[BH_ * NC_];

// bf16 split buffers (hi + lo ~ fp32 via 3x bf16 MMA)
__device__ __align__(16) __nv_bfloat16 g_xhi[B_ * L_ * D_];
__device__ __align__(16) __nv_bfloat16 g_xlo[B_ * L_ * D_];
__device__ __align__(16) __nv_bfloat16 g_whi[4 * D_ * D_];   // q,k,v,o
__device__ __align__(16) __nv_bfloat16 g_wlo[4 * D_ * D_];
__device__ __align__(16) __nv_bfloat16 g_chi[B_ * L_ * D_];
__device__ __align__(16) __nv_bfloat16 g_clo[B_ * L_ * D_];

// -------- helpers --------
__device__ __forceinline__ float warpSum(float v) {
#pragma unroll
    for (int o = 16; o > 0; o >>= 1) v += __shfl_xor_sync(0xffffffffu, v, o);
    return v;
}
__device__ __forceinline__ float warpMax(float v) {
#pragma unroll
    for (int o = 16; o > 0; o >>= 1) v = fmaxf(v, __shfl_xor_sync(0xffffffffu, v, o));
    return v;
}

// =====================================================================
// convert: fp32 -> (bf16 hi, bf16 lo)
// =====================================================================
__global__ void convert_split_kernel(const float* __restrict__ src,
                                     __nv_bfloat16* __restrict__ hi,
                                     __nv_bfloat16* __restrict__ lo) {
    int i = blockIdx.x * 256 + threadIdx.x;
    float4 v = ((const float4*)src)[i];
    __nv_bfloat16 h0 = __float2bfloat16(v.x);
    __nv_bfloat16 h1 = __float2bfloat16(v.y);
    __nv_bfloat16 h2 = __float2bfloat16(v.z);
    __nv_bfloat16 h3 = __float2bfloat16(v.w);
    __nv_bfloat16 l0 = __float2bfloat16(v.x - __bfloat162float(h0));
    __nv_bfloat16 l1 = __float2bfloat16(v.y - __bfloat162float(h1));
    __nv_bfloat16 l2 = __float2bfloat16(v.z - __bfloat162float(h2));
    __nv_bfloat16 l3 = __float2bfloat16(v.w - __bfloat162float(h3));
    __nv_bfloat162* H = (__nv_bfloat162*)hi;
    __nv_bfloat162* Lo = (__nv_bfloat162*)lo;
    H[2 * i] = __nv_bfloat162(h0, h1);
    H[2 * i + 1] = __nv_bfloat162(h2, h3);
    Lo[2 * i] = __nv_bfloat162(l0, l1);
    Lo[2 * i + 1] = __nv_bfloat162(l2, l3);
}

// all 4 weight matrices in one launch: grid = 4*64 blocks
__global__ void convert_w_kernel(const float* __restrict__ w0,
                                 const float* __restrict__ w1,
                                 const float* __restrict__ w2,
                                 const float* __restrict__ w3) {
    int mat = blockIdx.x >> 6;
    int i = (blockIdx.x & 63) * 256 + threadIdx.x;  // float4 index
    const float* src = (mat == 0) ? w0 : (mat == 1) ? w1 : (mat == 2) ? w2 : w3;
    float4 v = ((const float4*)src)[i];
    __nv_bfloat16 h0 = __float2bfloat16(v.x);
    __nv_bfloat16 h1 = __float2bfloat16(v.y);
    __nv_bfloat16 h2 = __float2bfloat16(v.z);
    __nv_bfloat16 h3 = __float2bfloat16(v.w);
    __nv_bfloat16 l0 = __float2bfloat16(v.x - __bfloat162float(h0));
    __nv_bfloat16 l1 = __float2bfloat16(v.y - __bfloat162float(h1));
    __nv_bfloat16 l2 = __float2bfloat16(v.z - __bfloat162float(h2));
    __nv_bfloat16 l3 = __float2bfloat16(v.w - __bfloat162float(h3));
    size_t o2 = (size_t)mat * (D_ * D_ / 2) + 2 * (size_t)i;
    __nv_bfloat162* H = (__nv_bfloat162*)g_whi;
    __nv_bfloat162* Lo = (__nv_bfloat162*)g_wlo;
    H[o2] = __nv_bfloat162(h0, h1);
    H[o2 + 1] = __nv_bfloat162(h2, h3);
    Lo[o2] = __nv_bfloat162(l0, l1);
    Lo[o2 + 1] = __nv_bfloat162(l2, l3);
}

// =====================================================================
// WMMA split-bf16 GEMM (unchanged R9 winner).
// =====================================================================
#define TM_ 128
#define TN_ 64
#define KSL 32
#define XP 40   // bf16 smem pitch
#define CP 72   // float epilogue pitch

__global__ __launch_bounds__(256)
void mma_gemm_kernel(const __nv_bfloat16* __restrict__ Ahi,
                     const __nv_bfloat16* __restrict__ Alo,
                     const float* __restrict__ bias0,
                     const float* __restrict__ bias1,
                     const float* __restrict__ bias2,
                     float* __restrict__ Out0,
                     float* __restrict__ Out1,
                     float* __restrict__ Out2,
                     int wbase, int mode) {
    __shared__ __align__(16) union {
        struct {
            __nv_bfloat16 xh[TM_ * XP];
            __nv_bfloat16 xl[TM_ * XP];
            __nv_bfloat16 wh[TN_ * XP];
            __nv_bfloat16 wl[TN_ * XP];
        } s;
        float cbuf[TM_ * CP];
    } u;

    const int tid = threadIdx.x;
    const int wid = tid >> 5;
    const int wm = wid & 3;
    const int wn = wid >> 2;
    const int rowBase = blockIdx.x * TM_;
    const int gc0 = blockIdx.y * TN_;
    const int mat = gc0 >> 8;
    const int colLoc = gc0 & 255;

    const __nv_bfloat16* Whi =
        g_whi + (size_t)(wbase + mat) * (D_ * D_) + (size_t)colLoc * D_;
    const __nv_bfloat16* Wlo =
        g_wlo + (size_t)(wbase + mat) * (D_ * D_) + (size_t)colLoc * D_;

    wmma::fragment<wmma::accumulator, 16, 16, 16, float> c[2][2];
#pragma unroll
    for (int i = 0; i < 2; i++)
#pragma unroll
        for (int j = 0; j < 2; j++) wmma::fill_fragment(c[i][j], 0.f);

    for (int s = 0; s < D_ / KSL; s++) {
        {
            const __nv_bfloat16* Ah = Ahi + (size_t)rowBase * D_ + s * KSL;
            const __nv_bfloat16* Al = Alo + (size_t)rowBase * D_ + s * KSL;
#pragma unroll
            for (int t = 0; t < 2; t++) {
                int i = tid + t * 256;
                int r = i >> 2, cg = (i & 3) * 8;
                *(uint4*)&u.s.xh[r * XP + cg] = *(const uint4*)(Ah + (size_t)r * D_ + cg);
                *(uint4*)&u.s.xl[r * XP + cg] = *(const uint4*)(Al + (size_t)r * D_ + cg);
            }
            const __nv_bfloat16* Bh = Whi + s * KSL;
            const __nv_bfloat16* Bl = Wlo + s * KSL;
            int r = tid >> 2, cg = (tid & 3) * 8;
            *(uint4*)&u.s.wh[r * XP + cg] = *(const uint4*)(Bh + (size_t)r * D_ + cg);
            *(uint4*)&u.s.wl[r * XP + cg] = *(const uint4*)(Bl + (size_t)r * D_ + cg);
        }
        __syncthreads();

#pragma unroll
        for (int kk = 0; kk < KSL; kk += 16) {
            wmma::fragment<wmma::matrix_a, 16, 16, 16, __nv_bfloat16, wmma::row_major> ah[2], al[2];
            wmma::fragment<wmma::matrix_b, 16, 16, 16, __nv_bfloat16, wmma::col_major> bh[2], bl[2];
#pragma unroll
            for (int i = 0; i < 2; i++) {
                wmma::load_matrix_sync(ah[i], &u.s.xh[(wm * 32 + i * 16) * XP + kk], XP);
                wmma::load_matrix_sync(al[i], &u.s.xl[(wm * 32 + i * 16) * XP + kk], XP);
            }
#pragma unroll
            for (int j = 0; j < 2; j++) {
                wmma::load_matrix_sync(bh[j], &u.s.wh[(wn * 32 + j * 16) * XP + kk], XP);
                wmma::load_matrix_sync(bl[j], &u.s.wl[(wn * 32 + j * 16) * XP + kk], XP);
            }
#pragma unroll
            for (int i = 0; i < 2; i++)
#pragma unroll
                for (int j = 0; j < 2; j++) {
                    wmma::mma_sync(c[i][j], ah[i], bh[j], c[i][j]);
                    wmma::mma_sync(c[i][j], ah[i], bl[j], c[i][j]);
                    wmma::mma_sync(c[i][j], al[i], bh[j], c[i][j]);
                }
        }
        __syncthreads();
    }

#pragma unroll
    for (int i = 0; i < 2; i++)
#pragma unroll
        for (int j = 0; j < 2; j++)
            wmma::store_matrix_sync(&u.cbuf[(wm * 32 + i * 16) * CP + wn * 32 + j * 16],
                                    c[i][j], CP, wmma::mem_row_major);
    __syncthreads();

    const float* Bv = (mat == 0) ? bias0 : (mat == 1) ? bias1 : bias2;
    float* Out = (mat == 0) ? Out0 : (mat == 1) ? Out1 : Out2;

#pragma unroll
    for (int t = 0; t < 8; t++) {
        int f = tid + t * 256;
        int r = f >> 4;
        int col = (f & 15) * 4;
        float4 o;
        o.x = u.cbuf[r * CP + col + 0] + Bv[colLoc + col + 0];
        o.y = u.cbuf[r * CP + col + 1] + Bv[colLoc + col + 1];
        o.z = u.cbuf[r * CP + col + 2] + Bv[colLoc + col + 2];
        o.w = u.cbuf[r * CP + col + 3] + Bv[colLoc + col + 3];
        int row = rowBase + r;
        if (mode == 0) {
            int b = row >> 11;
            int l = row & (L_ - 1);
            int gcol = gc0 + col;
            int head = (gcol >> 5) & 7;
            int e = gcol & 31;
            size_t ob = ((size_t)((b * H_ + head) * L_ + l)) * h_ + e;
            *(float4*)(Out + ob) = o;
        } else {
            *(float4*)(Out0 + (size_t)row * D_ + gc0 + col) = o;
        }
    }
}

// =====================================================================
// K2 (fused): pointwise + per-chunk partials, ILP-restructured.
// grid = BH*NC = 512 blocks, 256 threads (8 warps), 8 positions/warp.
// Gate: v̂ᵀMk̂ = (vᵀMk)/(‖k‖‖v‖) — raw inner runs before norms, then
// all 4 reductions finish in one interleaved butterfly.
// =====================================================================
__global__ void chunk_fused_kernel(const float* __restrict__ kv_scale,
                                   const float* __restrict__ qk_scale,
                                   const float* __restrict__ wg_w,
                                   const float* __restrict__ wg_b) {
    __shared__ float ks[C_][33];
    __shared__ float vs[C_][33];
    __shared__ float gsh[C_];
    __shared__ float simsh[C_];
    __shared__ float msh[h_ * 33];

    int c = blockIdx.x & (NC_ - 1);
    int bh = blockIdx.x >> 5;
    int head = bh & (H_ - 1);
    int base = bh * L_ + c * C_;
    int lane = threadIdx.x & 31;
    int w = threadIdx.x >> 5;

    for (int i = threadIdx.x; i < h_ * h_; i += 256)
        msh[(i >> 5) * 33 + (i & 31)] =
            wg_w[i] * kv_scale[(size_t)head * (h_ * h_) + i];
    __syncthreads();

    float Mreg[32];
#pragma unroll
    for (int e = 0; e < 32; e++) Mreg[e] = msh[lane * 33 + e];

    float qksc = qk_scale[head];
    float gb = wg_b[0];

#pragma unroll
    for (int j = 0; j < C_ / 8; j++) {
        int l = w * (C_ / 8) + j;
        size_t gidx = (size_t)(base + l) * h_ + lane;
        float q = g_Q[gidx];
        float k = g_K[gidx];
        float v = g_V[gidx];

        // raw gate inner on UN-normalized k (independent of norms)
        float inner = 0.f;
#pragma unroll
        for (int e = 0; e < 32; e++)
            inner = fmaf(Mreg[e], __shfl_sync(0xffffffffu, k, e), inner);

        // 4 independent reductions, interleaved butterfly
        float pqk = q * k, pkk = k * k, pvv = v * v, pvi = v * inner;
#pragma unroll
        for (int o = 16; o > 0; o >>= 1) {
            pqk += __shfl_xor_sync(0xffffffffu, pqk, o);
            pkk += __shfl_xor_sync(0xffffffffu, pkk, o);
            pvv += __shfl_xor_sync(0xffffffffu, pvv, o);
            pvi += __shfl_xor_sync(0xffffffffu, pvi, o);
        }
        float sim = pqk * qksc;
        float kn = fmaxf(sqrtf(pkk), 1e-12f);
        float vn = fmaxf(sqrtf(pvv), 1e-12f);
        k = k / kn;
        v = v / vn;
        float logit = pvi / (kn * vn) + gb;
        float r = fmaxf(logit, 0.f);
        float g = r * r + EPS_;

        ks[l][lane] = k;
        vs[l][lane] = v;
        g_K[gidx] = k;
        g_V[gidx] = v;
        if (lane == 0) {
            gsh[l] = g;
            simsh[l] = sim;
            g_gate[base + l] = g;
            g_sim[base + l] = sim;
        }
    }
    __syncthreads();

    // ---- Sdelta[d][e] = sum_i g_i v[i][d] k[i][e]; warp w: e=lane, d=w+8j
    float acc[4] = {0.f, 0.f, 0.f, 0.f};
    for (int i = 0; i < C_; i++) {
        float gk = gsh[i] * ks[i][lane];
#pragma unroll
        for (int j = 0; j < 4; j++) acc[j] += vs[i][w + 8 * j] * gk;
    }
    size_t sbase = (size_t)(bh * NC_ + c) * (h_ * h_);
#pragma unroll
    for (int j = 0; j < 4; j++) {
        int d = w + 8 * j;
        float sc = kv_scale[(size_t)head * (h_ * h_) + d * 32 + lane];
        g_Sdelta[sbase + d * 32 + lane] = acc[j] * sc;
    }

    if (threadIdx.x < 32) {
        float lm = -INFINITY, lg = 0.f;
#pragma unroll
        for (int j = 0; j < C_ / 32; j++) {
            lm = fmaxf(lm, simsh[lane + 32 * j]);
            lg += gsh[lane + 32 * j];
        }
        float mloc = warpMax(lm);
        float ls = 0.f;
#pragma unroll
        for (int j = 0; j < C_ / 32; j++) ls += expf(simsh[lane + 32 * j] - mloc);
        float sloc = warpSum(ls);
        float gsum = warpSum(lg);
        if (lane == 0) {
            int id = bh * NC_ + c;
            g_mloc[id] = mloc;
            g_sloc[id] = sloc;
            g_gsum[id] = gsum;
        }
    }
}

// =====================================================================
// K4: sequential exclusive scan over chunks. grid = BH = 16 blocks.
// =====================================================================
__global__ void chunk_scan_kernel() {
    int bh = blockIdx.x;
    int t = threadIdx.x;  // 256
    float acc[4] = {0.f, 0.f, 0.f, 0.f};
    for (int c = 0; c < NC_; c++) {
        size_t idx = (size_t)(bh * NC_ + c) * (h_ * h_);
#pragma unroll
        for (int j = 0; j < 4; j++) {
            g_Sprefix[idx + t + 256 * j] = acc[j];
            acc[j] += g_Sdelta[idx + t + 256 * j];
        }
    }
    if (t == 0) {
        float m = -INFINITY, s = 0.f, g = 0.f;
        for (int c = 0; c < NC_; c++) {
            int id = bh * NC_ + c;
            g_mpre[id] = m;
            g_spre[id] = s;
            g_gpre[id] = g;
            float mc = g_mloc[id], sc = g_sloc[id];
            float mn = fmaxf(m, mc);
            s = s * expf(m - mn) + sc * expf(mc - mn);
            m = mn;
            g += g_gsum[id];
        }
    }
}

// =====================================================================
// K5: chunk output. grid = BH*NC = 512 blocks, 256 threads.
// 4 threads per row l (8 output cols each); writes bf16 hi/lo split.
// =====================================================================
__global__ __launch_bounds__(256)
void chunk_output_kernel() {
    __shared__ float qs[C_ * P36];
    __shared__ float ksm[C_ * P36];
    __shared__ float vsm[C_ * P36];
    __shared__ float S0[h_ * P36];
    __shared__ float gsh[C_];
    __shared__ float simsh[C_];
    __shared__ float gcum[C_];
    __shared__ float msm[C_];
    __shared__ float ssm[C_];

    int c = blockIdx.x & (NC_ - 1);
    int bh = blockIdx.x >> 5;
    int head = bh & (H_ - 1);
    int b = bh >> 3;
    int base = bh * L_ + c * C_;
    int t = threadIdx.x;

    for (int i = t; i < C_ * h_; i += 256) {
        int l = i >> 5, d = i & 31;
        qs[l * P36 + d] = g_Q[(size_t)(base + l) * h_ + d];
        ksm[l * P36 + d] = g_K[(size_t)(base + l) * h_ + d];
        vsm[l * P36 + d] = g_V[(size_t)(base + l) * h_ + d];
    }
    size_t sbase = (size_t)(bh * NC_ + c) * (h_ * h_);
    for (int i = t; i < h_ * h_; i += 256) {
        int d = i >> 5, e = i & 31;
        S0[d * P36 + e] = g_Sprefix[sbase + i];
    }
    for (int i = t; i < C_; i += 256) {
        float gv = g_gate[base + i];
        float sv = g_sim[base + i];
        gsh[i] = gv;
        simsh[i] = sv;
        gcum[i] = gv;
        msm[i] = sv;
        ssm[i] = 1.f;
    }
    __syncthreads();

    for (int off = 1; off < C_; off <<= 1) {
        float ga = 0.f, m2 = 0.f, s2 = 0.f;
        bool rd = (t < C_) && (t >= off);
        if (rd) {
            ga = gcum[t - off];
            m2 = msm[t - off];
            s2 = ssm[t - off];
        }
        __syncthreads();
        if (rd) {
            gcum[t] += ga;
            float m1 = msm[t], s1 = ssm[t];
            float mn = fmaxf(m1, m2);
            ssm[t] = s1 * expf(m1 - mn) + s2 * expf(m2 - mn);
            msm[t] = mn;
        }
        __syncthreads();
    }

    int id = bh * NC_ + c;
    float m0 = g_mpre[id], s0 = g_spre[id], g0 = g_gpre[id];

    int l = t >> 2;
    int quad = t & 3;
    int eb = quad * 8;
    int lane = t & 31;
    unsigned gmask = 0xFu << (lane & ~3);

    float qf[32];
#pragma unroll
    for (int m = 0; m < 8; m++) {
        float4 qv = *(const float4*)&qs[l * P36 + m * 4];
        qf[m * 4 + 0] = qv.x;
        qf[m * 4 + 1] = qv.y;
        qf[m * 4 + 2] = qv.z;
        qf[m * 4 + 3] = qv.w;
    }

    float acc[8];
#pragma unroll
    for (int j = 0; j < 8; j++) acc[j] = 0.f;

#pragma unroll 8
    for (int d = 0; d < 32; d++) {
        float4 sa = *(const float4*)&S0[d * P36 + eb];
        float4 sb = *(const float4*)&S0[d * P36 + eb + 4];
        float qv = qf[d];
        acc[0] = fmaf(qv, sa.x, acc[0]);
        acc[1] = fmaf(qv, sa.y, acc[1]);
        acc[2] = fmaf(qv, sa.z, acc[2]);
        acc[3] = fmaf(qv, sa.w, acc[3]);
        acc[4] = fmaf(qv, sb.x, acc[4]);
        acc[5] = fmaf(qv, sb.y, acc[5]);
        acc[6] = fmaf(qv, sb.z, acc[6]);
        acc[7] = fmaf(qv, sb.w, acc[7]);
    }

    float qe0 = qf[eb + 0], qe1 = qf[eb + 1], qe2 = qf[eb + 2], qe3 = qf[eb + 3];
    float qe4 = qf[eb + 4], qe5 = qf[eb + 5], qe6 = qf[eb + 6], qe7 = qf[eb + 7];
    for (int i = 0; i <= l; i++) {
        float4 va = *(const float4*)&vsm[i * P36 + eb];
        float4 vb = *(const float4*)&vsm[i * P36 + eb + 4];
        float p = qe0 * va.x + qe1 * va.y + qe2 * va.z + qe3 * va.w +
                  qe4 * vb.x + qe5 * vb.y + qe6 * vb.z + qe7 * vb.w;
        p += __shfl_xor_sync(gmask, p, 1);
        p += __shfl_xor_sync(gmask, p, 2);
        p *= gsh[i];
        float4 ka = *(const float4*)&ksm[i * P36 + eb];
        float4 kb = *(const float4*)&ksm[i * P36 + eb + 4];
        acc[0] = fmaf(p, ka.x, acc[0]);
        acc[1] = fmaf(p, ka.y, acc[1]);
        acc[2] = fmaf(p, ka.z, acc[2]);
        acc[3] = fmaf(p, ka.w, acc[3]);
        acc[4] = fmaf(p, kb.x, acc[4]);
        acc[5] = fmaf(p, kb.y, acc[5]);
        acc[6] = fmaf(p, kb.z, acc[6]);
        acc[7] = fmaf(p, kb.w, acc[7]);
    }

    float ml = msm[l], sl = ssm[l];
    float mn = fmaxf(m0, ml);
    float sfull = s0 * expf(m0 - mn) + sl * expf(ml - mn);
    float ww = expf(simsh[l] - mn) / (sfull + EPS_);
    float silu = ww / (1.f + expf(-ww));
    float gc = gcum[l] + g0;
    float factor = (1.f + silu) / (gc + EPS_);

    // write ctxt directly as bf16 hi/lo split
    int lg = c * C_ + l;
    size_t obase = ((size_t)b * L_ + lg) * D_ + head * h_ + eb;
    __nv_bfloat16 hi8[8], lo8[8];
#pragma unroll
    for (int j = 0; j < 8; j++) {
        float o = acc[j] * factor;
        hi8[j] = __float2bfloat16(o);
        lo8[j] = __float2bfloat16(o - __bfloat162float(hi8[j]));
    }
    *(uint4*)(g_chi + obase) = *(uint4*)hi8;
    *(uint4*)(g_clo + obase) = *(uint4*)lo8;
}

// =====================================================================
// launch
// =====================================================================
extern "C" void kernel_launch(void* const* d_in, const int* in_sizes, int n_in,
                              void* d_out, int out_size) {
    const float* x = (const float*)d_in[0];
    const float* wq_w = (const float*)d_in[1];
    const float* wq_b = (const float*)d_in[2];
    const float* wk_w = (const float*)d_in[3];
    const float* wk_b = (const float*)d_in[4];
    const float* wv_w = (const float*)d_in[5];
    const float* wv_b = (const float*)d_in[6];
    const float* wo_w = (const float*)d_in[7];
    const float* wo_b = (const float*)d_in[8];
    const float* wg_w = (const float*)d_in[9];
    const float* wg_b = (const float*)d_in[10];
    const float* kv_scale = (const float*)d_in[11];
    const float* qk_scale = (const float*)d_in[12];
    float* out = (float*)d_out;

    float* Qp; cudaGetSymbolAddress((void**)&Qp, g_Q);
    float* Kp; cudaGetSymbolAddress((void**)&Kp, g_K);
    float* Vp; cudaGetSymbolAddress((void**)&Vp, g_V);
    __nv_bfloat16* xhi; cudaGetSymbolAddress((void**)&xhi, g_xhi);
    __nv_bfloat16* xlo; cudaGetSymbolAddress((void**)&xlo, g_xlo);
    __nv_bfloat16* chi; cudaGetSymbolAddress((void**)&chi, g_chi);
    __nv_bfloat16* clo; cudaGetSymbolAddress((void**)&clo, g_clo);

    // converts
    convert_split_kernel<<<(B_ * L_ * D_) / 4 / 256, 256>>>(x, xhi, xlo);
    convert_w_kernel<<<4 * 64, 256>>>(wq_w, wk_w, wv_w, wo_w);

    // fused QKV projection (WMMA bf16 split)
    dim3 gqkv(B_ * L_ / TM_, 3 * D_ / TN_);
    mma_gemm_kernel<<<gqkv, 256>>>(xhi, xlo, wq_b, wk_b, wv_b,
                                   Qp, Kp, Vp, 0, 0);

    chunk_fused_kernel<<<BH_ * NC_, 256>>>(kv_scale, qk_scale, wg_w, wg_b);
    chunk_scan_kernel<<<BH_, 256>>>();
    chunk_output_kernel<<<BH_ * NC_, 256>>>();

    // output projection (reads chi/clo written by chunk_output)
    dim3 gout(B_ * L_ / TM_, D_ / TN_);
    mma_gemm_kernel<<<gout, 256>>>(chi, clo, wo_b, wo_b, wo_b,
                                   out, out, out, 3, 1);
}